// round 1
// baseline (speedup 1.0000x reference)
#include <cuda_runtime.h>
#include <cfloat>

#define NN   8192
#define FEA  192
#define HID  256
#define CLS  1000
#define KNB  9
#define BATCH 16

typedef unsigned long long u64;

// ---------------- scratch (device globals: no allocation at runtime) --------
__device__ float g_sq[NN];
__device__ float g_D[(long long)NN * NN];      // 256 MB distance matrix
__device__ int   g_idx[NN * KNB];
__device__ float g_agg[NN * HID];              // holds up to 8192 x 256
__device__ float g_h1[NN * HID];
__device__ float g_h2[NN * HID];
__device__ float g_h3[NN * CLS];

// ---------------- packed f32x2 helpers --------------------------------------
__device__ __forceinline__ u64 pk2(float lo, float hi) {
    u64 r; asm("mov.b64 %0,{%1,%2};" : "=l"(r) : "f"(lo), "f"(hi)); return r;
}
__device__ __forceinline__ void upk2(u64 v, float& lo, float& hi) {
    asm("mov.b64 {%0,%1},%2;" : "=f"(lo), "=f"(hi) : "l"(v));
}
__device__ __forceinline__ void fma2(u64& d, u64 a, u64 b) {
    asm("fma.rn.f32x2 %0,%1,%2,%0;" : "+l"(d) : "l"(a), "l"(b));
}

// ---------------- row squared norms ------------------------------------------
__global__ void sq_kernel(const float* __restrict__ x) {
    int warp = (blockIdx.x * blockDim.x + threadIdx.x) >> 5;
    int lane = threadIdx.x & 31;
    if (warp >= NN) return;
    const float* r = x + (size_t)warp * FEA;
    float s = 0.f;
    for (int c = lane; c < FEA; c += 32) { float v = r[c]; s += v * v; }
    #pragma unroll
    for (int o = 16; o; o >>= 1) s += __shfl_xor_sync(0xffffffffu, s, o);
    if (lane == 0) g_sq[warp] = s;
}

// ---------------- symmetric distance GEMM ------------------------------------
// block tile 128x128, 256 threads, 8x8 per thread (m-paired f32x2 accumulators)
__global__ __launch_bounds__(256) void dist_kernel(const float* __restrict__ x) {
    int bj = blockIdx.x, bi = blockIdx.y;
    if (bi > bj) return;                   // only upper triangle of tiles
    __shared__ __align__(16) float sm[8256];   // As[16][128] | Bs[16][128]; reused as 64x129 stage
    float* As = sm;
    float* Bs = sm + 2048;
    int t = threadIdx.x;
    int tm = t >> 4, tn = t & 15;

    u64 acc[4][8];
    #pragma unroll
    for (int a = 0; a < 4; a++)
        #pragma unroll
        for (int b = 0; b < 8; b++) acc[a][b] = 0ull;

    for (int k0 = 0; k0 < FEA; k0 += 16) {
        #pragma unroll
        for (int q = 0; q < 2; q++) {
            int l = t * 2 + q;
            int row = l >> 2, kq = (l & 3) << 2;
            float4 va = *(const float4*)(x + (size_t)(bi * 128 + row) * FEA + k0 + kq);
            As[(kq + 0) * 128 + row] = va.x;
            As[(kq + 1) * 128 + row] = va.y;
            As[(kq + 2) * 128 + row] = va.z;
            As[(kq + 3) * 128 + row] = va.w;
            float4 vb = *(const float4*)(x + (size_t)(bj * 128 + row) * FEA + k0 + kq);
            Bs[(kq + 0) * 128 + row] = vb.x;
            Bs[(kq + 1) * 128 + row] = vb.y;
            Bs[(kq + 2) * 128 + row] = vb.z;
            Bs[(kq + 3) * 128 + row] = vb.w;
        }
        __syncthreads();
        #pragma unroll
        for (int kk = 0; kk < 16; kk++) {
            u64 a2[4];
            #pragma unroll
            for (int m = 0; m < 4; m++)
                a2[m] = *(const u64*)&As[kk * 128 + tm * 8 + 2 * m];
            #pragma unroll
            for (int n = 0; n < 8; n++) {
                float bv = Bs[kk * 128 + tn * 8 + n];
                u64 bb = pk2(bv, bv);
                #pragma unroll
                for (int m = 0; m < 4; m++) fma2(acc[m][n], a2[m], bb);
            }
        }
        __syncthreads();
    }

    float sqA[8], sqB[8];
    #pragma unroll
    for (int m = 0; m < 8; m++) sqA[m] = g_sq[bi * 128 + tm * 8 + m];
    #pragma unroll
    for (int n = 0; n < 8; n++) sqB[n] = g_sq[bj * 128 + tn * 8 + n];

    // direct tile (coalesced float4 writes)
    #pragma unroll
    for (int m2 = 0; m2 < 4; m2++) {
        float r0v[8], r1v[8];
        #pragma unroll
        for (int n = 0; n < 8; n++) {
            float f0, f1; upk2(acc[m2][n], f0, f1);
            r0v[n] = sqA[2 * m2]     + sqB[n] - 2.f * f0;
            r1v[n] = sqA[2 * m2 + 1] + sqB[n] - 2.f * f1;
        }
        size_t o0 = (size_t)(bi * 128 + tm * 8 + 2 * m2) * NN + bj * 128 + tn * 8;
        *(float4*)(g_D + o0)      = make_float4(r0v[0], r0v[1], r0v[2], r0v[3]);
        *(float4*)(g_D + o0 + 4)  = make_float4(r0v[4], r0v[5], r0v[6], r0v[7]);
        size_t o1 = o0 + NN;
        *(float4*)(g_D + o1)      = make_float4(r1v[0], r1v[1], r1v[2], r1v[3]);
        *(float4*)(g_D + o1 + 4)  = make_float4(r1v[4], r1v[5], r1v[6], r1v[7]);
    }

    // transposed tile via smem staging (two 64-row passes)
    if (bi != bj) {
        #pragma unroll
        for (int p = 0; p < 2; p++) {
            __syncthreads();
            if ((tn >> 3) == p) {
                int jb = (tn & 7) * 8;
                #pragma unroll
                for (int n = 0; n < 8; n++) {
                    #pragma unroll
                    for (int m2 = 0; m2 < 4; m2++) {
                        float f0, f1; upk2(acc[m2][n], f0, f1);
                        sm[(jb + n) * 129 + tm * 8 + 2 * m2]     = sqA[2 * m2]     + sqB[n] - 2.f * f0;
                        sm[(jb + n) * 129 + tm * 8 + 2 * m2 + 1] = sqA[2 * m2 + 1] + sqB[n] - 2.f * f1;
                    }
                }
            }
            __syncthreads();
            #pragma unroll
            for (int w = 0; w < 8; w++) {
                int e = t + w * 256;
                int r = e >> 5, c4 = (e & 31) << 2;
                float4 vv = make_float4(sm[r * 129 + c4], sm[r * 129 + c4 + 1],
                                        sm[r * 129 + c4 + 2], sm[r * 129 + c4 + 3]);
                *(float4*)(g_D + (size_t)(bj * 128 + p * 64 + r) * NN + bi * 128 + c4) = vv;
            }
        }
    }
}

// ---------------- per-row top-9 smallest -------------------------------------
__global__ __launch_bounds__(256) void topk_kernel() {
    int i = blockIdx.x;
    const float* __restrict__ row = g_D + (size_t)i * NN;
    int t = threadIdx.x;
    float v[KNB]; int id[KNB];
    #pragma unroll
    for (int q = 0; q < KNB; q++) { v[q] = FLT_MAX; id[q] = 0x7fffffff; }
    for (int j = t; j < NN; j += 256) {
        float d = __ldg(row + j);
        if (d < v[KNB - 1]) {
            v[KNB - 1] = d; id[KNB - 1] = j;
            #pragma unroll
            for (int q = KNB - 1; q > 0; q--) {
                if (v[q] < v[q - 1]) {
                    float tv = v[q]; v[q] = v[q - 1]; v[q - 1] = tv;
                    int ti = id[q]; id[q] = id[q - 1]; id[q - 1] = ti;
                }
            }
        }
    }
    __shared__ float rv[256]; __shared__ int rj[256]; __shared__ int rt[256];
    int p = 0;
    for (int r = 0; r < KNB; r++) {
        rv[t] = (p < KNB) ? v[p] : FLT_MAX;
        rj[t] = (p < KNB) ? id[p] : 0x7fffffff;
        rt[t] = t;
        __syncthreads();
        for (int s = 128; s > 0; s >>= 1) {
            if (t < s) {
                bool take = (rv[t + s] < rv[t]) ||
                            (rv[t + s] == rv[t] && rj[t + s] < rj[t]);
                if (take) { rv[t] = rv[t + s]; rj[t] = rj[t + s]; rt[t] = rt[t + s]; }
            }
            __syncthreads();
        }
        if (t == 0) g_idx[i * KNB + r] = rj[0];
        if (rt[0] == t) p++;
        __syncthreads();
    }
}

// ---------------- gather + mean over 9 neighbors -----------------------------
__global__ void gather_mean(const float* __restrict__ h, int C, float* __restrict__ agg) {
    int i = blockIdx.x;
    int c = threadIdx.x;
    if (c >= C) return;
    const int* idp = g_idx + i * KNB;
    float s = 0.f;
    #pragma unroll
    for (int j = 0; j < KNB; j++) s += __ldg(h + (size_t)idp[j] * C + c);
    agg[(size_t)i * C + c] = s * (1.0f / 9.0f);
}

// ---------------- fused dual GEMM: relu(Ag@Wl + Hh@Wr + b) --------------------
// block tile 128x128, 256 threads, 8x8 per thread
__global__ __launch_bounds__(256) void sage_gemm(
    const float* __restrict__ Ag, const float* __restrict__ Hh,
    const float* __restrict__ Wl, const float* __restrict__ Wr,
    const float* __restrict__ bias, float* __restrict__ O,
    int K1, int Nn)
{
    int bn = blockIdx.x, bm = blockIdx.y;
    __shared__ __align__(16) float As[16 * 128];
    __shared__ __align__(16) float Bs[16 * 128];
    int t = threadIdx.x;
    int tm = t >> 4, tn = t & 15;

    u64 acc[4][8];
    #pragma unroll
    for (int a = 0; a < 4; a++)
        #pragma unroll
        for (int b = 0; b < 8; b++) acc[a][b] = 0ull;

    for (int ph = 0; ph < 2; ph++) {
        const float* A = ph ? Hh : Ag;
        const float* W = ph ? Wr : Wl;
        for (int k0 = 0; k0 < K1; k0 += 16) {
            #pragma unroll
            for (int q = 0; q < 2; q++) {
                int l = t * 2 + q;
                {   // A tile: rows of Ag/Hh
                    int row = l >> 2, kq = (l & 3) << 2;
                    float4 va = *(const float4*)(A + (size_t)(bm * 128 + row) * K1 + k0 + kq);
                    As[(kq + 0) * 128 + row] = va.x;
                    As[(kq + 1) * 128 + row] = va.y;
                    As[(kq + 2) * 128 + row] = va.z;
                    As[(kq + 3) * 128 + row] = va.w;
                }
                {   // W tile: [16 x 128] slab of [K1 x Nn], guard Nn edge
                    int krow = l >> 5, c4 = (l & 31) << 2;
                    int col = bn * 128 + c4;
                    float4 vb;
                    if (col + 3 < Nn) {
                        vb = *(const float4*)(W + (size_t)(k0 + krow) * Nn + col);
                    } else {
                        vb.x = (col + 0 < Nn) ? W[(size_t)(k0 + krow) * Nn + col + 0] : 0.f;
                        vb.y = (col + 1 < Nn) ? W[(size_t)(k0 + krow) * Nn + col + 1] : 0.f;
                        vb.z = (col + 2 < Nn) ? W[(size_t)(k0 + krow) * Nn + col + 2] : 0.f;
                        vb.w = (col + 3 < Nn) ? W[(size_t)(k0 + krow) * Nn + col + 3] : 0.f;
                    }
                    *(float4*)&Bs[krow * 128 + c4] = vb;
                }
            }
            __syncthreads();
            #pragma unroll
            for (int kk = 0; kk < 16; kk++) {
                u64 a2[4];
                #pragma unroll
                for (int m = 0; m < 4; m++)
                    a2[m] = *(const u64*)&As[kk * 128 + tm * 8 + 2 * m];
                #pragma unroll
                for (int n = 0; n < 8; n++) {
                    float bv = Bs[kk * 128 + tn * 8 + n];
                    u64 bb = pk2(bv, bv);
                    #pragma unroll
                    for (int m = 0; m < 4; m++) fma2(acc[m][n], a2[m], bb);
                }
            }
            __syncthreads();
        }
    }

    #pragma unroll
    for (int m2 = 0; m2 < 4; m2++) {
        int r0 = bm * 128 + tm * 8 + 2 * m2;
        #pragma unroll
        for (int n = 0; n < 8; n++) {
            int col = bn * 128 + tn * 8 + n;
            if (col < Nn) {
                float f0, f1; upk2(acc[m2][n], f0, f1);
                float bb = bias[col];
                float o0 = f0 + bb; o0 = o0 > 0.f ? o0 : 0.f;
                float o1 = f1 + bb; o1 = o1 > 0.f ? o1 : 0.f;
                O[(size_t)r0 * Nn + col]       = o0;
                O[(size_t)(r0 + 1) * Nn + col] = o1;
            }
        }
    }
}

// ---------------- mean pool over 512-node segments ---------------------------
__global__ void pool_kernel(const float* __restrict__ h3, float* __restrict__ out) {
    int b = blockIdx.x;
    int chunk = blockIdx.y;
    int t = threadIdx.x;
    int o = chunk * 125 + t;
    if (t >= 125) return;
    const float* p = h3 + (size_t)(b * 512) * CLS + o;
    float s = 0.f;
    for (int r = 0; r < 512; r++) s += p[(size_t)r * CLS];
    out[b * CLS + o] = s * (1.0f / 512.0f);
}

// ---------------- launch -----------------------------------------------------
extern "C" void kernel_launch(void* const* d_in, const int* in_sizes, int n_in,
                              void* d_out, int out_size) {
    const float* x   = (const float*)d_in[0];
    const float* wl0 = (const float*)d_in[1];
    const float* bl0 = (const float*)d_in[2];
    const float* wr0 = (const float*)d_in[3];
    const float* wl1 = (const float*)d_in[4];
    const float* bl1 = (const float*)d_in[5];
    const float* wr1 = (const float*)d_in[6];
    const float* wl2 = (const float*)d_in[7];
    const float* bl2 = (const float*)d_in[8];
    const float* wr2 = (const float*)d_in[9];
    float* out = (float*)d_out;

    float *p_agg, *p_h1, *p_h2, *p_h3;
    cudaGetSymbolAddress((void**)&p_agg, g_agg);
    cudaGetSymbolAddress((void**)&p_h1,  g_h1);
    cudaGetSymbolAddress((void**)&p_h2,  g_h2);
    cudaGetSymbolAddress((void**)&p_h3,  g_h3);

    sq_kernel<<<NN / 8, 256>>>(x);
    dist_kernel<<<dim3(64, 64), 256>>>(x);
    topk_kernel<<<NN, 256>>>();

    // layer 0: agg from x (C=192)
    gather_mean<<<NN, FEA>>>(x, FEA, p_agg);
    sage_gemm<<<dim3(2, 64), 256>>>(p_agg, x, wl0, wr0, bl0, p_h1, FEA, HID);

    // layer 1
    gather_mean<<<NN, HID>>>(p_h1, HID, p_agg);
    sage_gemm<<<dim3(2, 64), 256>>>(p_agg, p_h1, wl1, wr1, bl1, p_h2, HID, HID);

    // layer 2
    gather_mean<<<NN, HID>>>(p_h2, HID, p_agg);
    sage_gemm<<<dim3(8, 64), 256>>>(p_agg, p_h2, wl2, wr2, bl2, p_h3, HID, CLS);

    pool_kernel<<<dim3(BATCH, 8), 128>>>(p_h3, out);
}

// round 2
// speedup vs baseline: 1.4414x; 1.4414x over previous
#include <cuda_runtime.h>
#include <cuda_bf16.h>
#include <cfloat>

#define NN   8192
#define FEA  192
#define HID  256
#define CLS  1000
#define CLSP 1024
#define KNB  9
#define KSTR 512          // activation-cat buffer k-stride (bf16 elems)

typedef unsigned int u32;
typedef __nv_bfloat16 bf16;

// ---------------- scratch ----------------------------------------------------
__device__ float g_sq[NN];
__device__ float g_D[(long long)NN * NN];          // 256 MB
__device__ int   g_idx[NN * KNB];
__device__ bf16  g_c0h[NN * KSTR], g_c0l[NN * KSTR];   // cat buffer 0 (hi/lo)
__device__ bf16  g_c1h[NN * KSTR], g_c1l[NN * KSTR];   // cat buffer 1 (hi/lo)
__device__ bf16  g_w0h[256 * 384],  g_w0l[256 * 384];  // WT0 [Npad=256][Ktot=384]
__device__ bf16  g_w1h[256 * 512],  g_w1l[256 * 512];  // WT1 [256][512]
__device__ bf16  g_w2h[1024 * 512], g_w2l[1024 * 512]; // WT2 [1024][512]
__device__ float g_h1[NN * HID];
__device__ float g_h2[NN * HID];
__device__ float g_h3[NN * CLSP];

// ---------------- helpers ----------------------------------------------------
__device__ __forceinline__ u32 s2u(const void* p) {
    u32 a;
    asm("{.reg .u64 t; cvta.to.shared.u64 t, %1; cvt.u32.u64 %0, t;}" : "=r"(a) : "l"(p));
    return a;
}
__device__ __forceinline__ void cpa16(u32 dst, const void* src) {
    asm volatile("cp.async.cg.shared.global [%0], [%1], 16;" :: "r"(dst), "l"(src));
}
__device__ __forceinline__ void ldsm4(u32* r, u32 addr) {
    asm volatile("ldmatrix.sync.aligned.m8n8.x4.shared.b16 {%0,%1,%2,%3}, [%4];"
        : "=r"(r[0]), "=r"(r[1]), "=r"(r[2]), "=r"(r[3]) : "r"(addr));
}
__device__ __forceinline__ void mma16816(float* c, const u32* a, const u32* b) {
    asm volatile("mma.sync.aligned.m16n8k16.row.col.f32.bf16.bf16.f32 "
        "{%0,%1,%2,%3},{%4,%5,%6,%7},{%8,%9},{%0,%1,%2,%3};"
        : "+f"(c[0]), "+f"(c[1]), "+f"(c[2]), "+f"(c[3])
        : "r"(a[0]), "r"(a[1]), "r"(a[2]), "r"(a[3]), "r"(b[0]), "r"(b[1]));
}
__device__ __forceinline__ void splt(float v, bf16& h, bf16& l) {
    h = __float2bfloat16_rn(v);
    l = __float2bfloat16_rn(v - __bfloat162float(h));
}

// tile loader: [128 rows x 32 k] bf16 into smem (row stride 40 bf16 = 80B)
__device__ __forceinline__ void ldtile(u32 dstb, const bf16* g, int row0, int ld, int k0, int t) {
    #pragma unroll
    for (int q = 0; q < 2; q++) {
        int id = t * 2 + q;
        int row = id >> 2, kq = id & 3;
        cpa16(dstb + row * 80 + kq * 16, g + (size_t)(row0 + row) * ld + k0 + kq * 8);
    }
}

#define TB 10240   // one tile: 128*40*2 bytes

// ---------------- small kernels ----------------------------------------------
__global__ void sq_kernel(const float* __restrict__ x) {
    int warp = (blockIdx.x * blockDim.x + threadIdx.x) >> 5;
    int lane = threadIdx.x & 31;
    if (warp >= NN) return;
    const float* r = x + (size_t)warp * FEA;
    float s = 0.f;
    for (int c = lane; c < FEA; c += 32) { float v = r[c]; s += v * v; }
    #pragma unroll
    for (int o = 16; o; o >>= 1) s += __shfl_xor_sync(0xffffffffu, s, o);
    if (lane == 0) g_sq[warp] = s;
}

__global__ void xsplit_kernel(const float* __restrict__ x) {
    int i = blockIdx.x * 256 + threadIdx.x;
    if (i >= NN * FEA) return;
    int r = i / FEA, c = i % FEA;
    bf16 h, l; splt(x[i], h, l);
    g_c0h[(size_t)r * KSTR + 192 + c] = h;
    g_c0l[(size_t)r * KSTR + 192 + c] = l;
}

__global__ void wt_build(const float* __restrict__ Wl, const float* __restrict__ Wr,
                         int K1, int Nn, int Npad, bf16* __restrict__ WTh, bf16* __restrict__ WTl) {
    int Ktot = 2 * K1;
    int idx = blockIdx.x * 256 + threadIdx.x;
    if (idx >= Npad * Ktot) return;
    int n = idx / Ktot, k = idx % Ktot;
    float v = 0.f;
    if (n < Nn) v = (k < K1) ? Wl[(size_t)k * Nn + n] : Wr[(size_t)(k - K1) * Nn + n];
    bf16 h, l; splt(v, h, l);
    WTh[idx] = h; WTl[idx] = l;
}

// ---------------- distance GEMM (tensor cores, bf16x3) ------------------------
__global__ __launch_bounds__(256, 1) void dist_mma(const bf16* __restrict__ Xh,
                                                   const bf16* __restrict__ Xl) {
    int bj = blockIdx.x, bi = blockIdx.y;
    if (bi > bj) return;
    extern __shared__ char smem[];
    u32 sb = s2u(smem);
    int t = threadIdx.x, lane = t & 31, warp = t >> 5;
    int wm = warp & 1, wn = warp >> 1;

    float acc[4][4][4] = {};

    const int NC = FEA / 32;   // 6
    ldtile(sb + 0 * TB, Xh, bi * 128, KSTR, 0, t);
    ldtile(sb + 1 * TB, Xl, bi * 128, KSTR, 0, t);
    ldtile(sb + 2 * TB, Xh, bj * 128, KSTR, 0, t);
    ldtile(sb + 3 * TB, Xl, bj * 128, KSTR, 0, t);
    asm volatile("cp.async.commit_group;");

    for (int c = 0; c < NC; c++) {
        if (c + 1 < NC) {
            u32 bb = sb + ((c + 1) & 1) * 4 * TB;
            int k0 = (c + 1) * 32;
            ldtile(bb + 0 * TB, Xh, bi * 128, KSTR, k0, t);
            ldtile(bb + 1 * TB, Xl, bi * 128, KSTR, k0, t);
            ldtile(bb + 2 * TB, Xh, bj * 128, KSTR, k0, t);
            ldtile(bb + 3 * TB, Xl, bj * 128, KSTR, k0, t);
            asm volatile("cp.async.commit_group;");
            asm volatile("cp.async.wait_group 1;");
        } else {
            asm volatile("cp.async.wait_group 0;");
        }
        __syncthreads();
        u32 base = sb + (c & 1) * 4 * TB;
        u32 aH = base, aL = base + TB, bH = base + 2 * TB, bL = base + 3 * TB;
        #pragma unroll
        for (int kk = 0; kk < 32; kk += 16) {
            u32 AH[4][4], AL[4][4], BH[4][2], BL[4][2];
            #pragma unroll
            for (int mt = 0; mt < 4; mt++) {
                u32 ro = (u32)((wm * 64 + mt * 16 + (lane & 15)) * 80 + (kk + (lane >> 4) * 8) * 2);
                ldsm4(AH[mt], aH + ro);
                ldsm4(AL[mt], aL + ro);
            }
            #pragma unroll
            for (int np = 0; np < 2; np++) {
                u32 ro = (u32)((wn * 32 + np * 16 + ((lane >> 4) * 8) + (lane & 7)) * 80
                               + (kk + ((lane >> 3) & 1) * 8) * 2);
                u32 r[4];
                ldsm4(r, bH + ro);
                BH[2 * np][0] = r[0]; BH[2 * np][1] = r[1];
                BH[2 * np + 1][0] = r[2]; BH[2 * np + 1][1] = r[3];
                ldsm4(r, bL + ro);
                BL[2 * np][0] = r[0]; BL[2 * np][1] = r[1];
                BL[2 * np + 1][0] = r[2]; BL[2 * np + 1][1] = r[3];
            }
            #pragma unroll
            for (int mt = 0; mt < 4; mt++)
                #pragma unroll
                for (int nt = 0; nt < 4; nt++) {
                    mma16816(acc[mt][nt], AH[mt], BH[nt]);
                    mma16816(acc[mt][nt], AH[mt], BL[nt]);
                    mma16816(acc[mt][nt], AL[mt], BH[nt]);
                }
        }
        __syncthreads();
    }

    // epilogue: d = sq[i] + sq[j] - 2*dot ; write direct + transposed tile
    float* smf = (float*)smem;   // [128][132] stage for transposed tile
    bool diag = (bi == bj);
    #pragma unroll
    for (int mt = 0; mt < 4; mt++) {
        int rl0 = wm * 64 + mt * 16 + (lane >> 2);
        #pragma unroll
        for (int nt = 0; nt < 4; nt++) {
            int cl = wn * 32 + nt * 8 + (lane & 3) * 2;
            float sqc0 = g_sq[bj * 128 + cl], sqc1 = g_sq[bj * 128 + cl + 1];
            #pragma unroll
            for (int h = 0; h < 2; h++) {
                int rl = rl0 + h * 8;
                float sr = g_sq[bi * 128 + rl];
                float d0 = sr + sqc0 - 2.f * acc[mt][nt][2 * h + 0];
                float d1 = sr + sqc1 - 2.f * acc[mt][nt][2 * h + 1];
                float2 dv = make_float2(d0, d1);
                *(float2*)(g_D + (size_t)(bi * 128 + rl) * NN + bj * 128 + cl) = dv;
                if (!diag) {
                    smf[cl * 132 + rl] = d0;
                    smf[(cl + 1) * 132 + rl] = d1;
                }
            }
        }
    }
    if (!diag) {
        __syncthreads();
        #pragma unroll
        for (int w = 0; w < 16; w++) {
            int e = t + w * 256;          // 4096 float4 = 128x128
            int r = e >> 5, c4 = (e & 31) << 2;
            float4 v = make_float4(smf[r * 132 + c4], smf[r * 132 + c4 + 1],
                                   smf[r * 132 + c4 + 2], smf[r * 132 + c4 + 3]);
            *(float4*)(g_D + (size_t)(bj * 128 + r) * NN + bi * 128 + c4) = v;
        }
    }
}

// ---------------- per-row top-9 smallest --------------------------------------
__global__ __launch_bounds__(256) void topk_kernel() {
    int i = blockIdx.x;
    const float4* __restrict__ row = (const float4*)(g_D + (size_t)i * NN);
    int t = threadIdx.x;
    float v[KNB]; int id[KNB];
    #pragma unroll
    for (int q = 0; q < KNB; q++) { v[q] = FLT_MAX; id[q] = 0x7fffffff; }
    for (int j4 = t; j4 < NN / 4; j4 += 256) {
        float4 dv = __ldg(row + j4);
        float vv[4] = {dv.x, dv.y, dv.z, dv.w};
        #pragma unroll
        for (int e = 0; e < 4; e++) {
            float d = vv[e];
            if (d < v[KNB - 1]) {
                int j = j4 * 4 + e;
                v[KNB - 1] = d; id[KNB - 1] = j;
                #pragma unroll
                for (int q = KNB - 1; q > 0; q--) {
                    if (v[q] < v[q - 1]) {
                        float tv = v[q]; v[q] = v[q - 1]; v[q - 1] = tv;
                        int ti = id[q]; id[q] = id[q - 1]; id[q - 1] = ti;
                    }
                }
            }
        }
    }
    __shared__ float rv[256]; __shared__ int rj[256]; __shared__ int rt[256];
    int p = 0;
    for (int r = 0; r < KNB; r++) {
        rv[t] = (p < KNB) ? v[p] : FLT_MAX;
        rj[t] = (p < KNB) ? id[p] : 0x7fffffff;
        rt[t] = t;
        __syncthreads();
        for (int s = 128; s > 0; s >>= 1) {
            if (t < s) {
                bool take = (rv[t + s] < rv[t]) ||
                            (rv[t + s] == rv[t] && rj[t + s] < rj[t]);
                if (take) { rv[t] = rv[t + s]; rj[t] = rj[t + s]; rt[t] = rt[t + s]; }
            }
            __syncthreads();
        }
        if (t == 0) g_idx[i * KNB + r] = rj[0];
        if (rt[0] == t) p++;
        __syncthreads();
    }
}

// ---------------- gather + mean -> bf16 hi/lo split ---------------------------
__global__ void gather_split(const float* __restrict__ h, int C,
                             bf16* __restrict__ oh, bf16* __restrict__ ol) {
    int row = blockIdx.x * 4 + threadIdx.y;
    int c4 = threadIdx.x * 4;
    const int* idp = g_idx + row * KNB;
    float4 s = make_float4(0.f, 0.f, 0.f, 0.f);
    #pragma unroll
    for (int j = 0; j < KNB; j++) {
        float4 v = __ldg((const float4*)(h + (size_t)idp[j] * C + c4));
        s.x += v.x; s.y += v.y; s.z += v.z; s.w += v.w;
    }
    const float inv = 1.0f / 9.0f;
    float vv[4] = {s.x * inv, s.y * inv, s.z * inv, s.w * inv};
    size_t off = (size_t)row * KSTR + c4;
    #pragma unroll
    for (int e = 0; e < 4; e += 2) {
        bf16 h0, l0, h1, l1;
        splt(vv[e], h0, l0); splt(vv[e + 1], h1, l1);
        __nv_bfloat162 ph; ph.x = h0; ph.y = h1;
        __nv_bfloat162 pl; pl.x = l0; pl.y = l1;
        *(__nv_bfloat162*)(oh + off + e) = ph;
        *(__nv_bfloat162*)(ol + off + e) = pl;
    }
}

// ---------------- SAGE dual-GEMM: relu([agg|h]@[Wl;Wr] + b) -------------------
__global__ __launch_bounds__(256, 1) void sage_mma(
    const bf16* __restrict__ Ah, const bf16* __restrict__ Al, int Ktot,
    const bf16* __restrict__ Bh, const bf16* __restrict__ Bl,
    const float* __restrict__ bias, int Nbias,
    float* __restrict__ O, int Nstr,
    bf16* __restrict__ Sh, bf16* __restrict__ Sl)
{
    int bn = blockIdx.x, bm = blockIdx.y;
    extern __shared__ char smem[];
    u32 sb = s2u(smem);
    int t = threadIdx.x, lane = t & 31, warp = t >> 5;
    int wm = warp & 1, wn = warp >> 1;

    float acc[4][4][4] = {};

    int nc = Ktot / 32;
    ldtile(sb + 0 * TB, Ah, bm * 128, KSTR, 0, t);
    ldtile(sb + 1 * TB, Al, bm * 128, KSTR, 0, t);
    ldtile(sb + 2 * TB, Bh, bn * 128, Ktot, 0, t);
    ldtile(sb + 3 * TB, Bl, bn * 128, Ktot, 0, t);
    asm volatile("cp.async.commit_group;");

    for (int c = 0; c < nc; c++) {
        if (c + 1 < nc) {
            u32 bb = sb + ((c + 1) & 1) * 4 * TB;
            int k0 = (c + 1) * 32;
            ldtile(bb + 0 * TB, Ah, bm * 128, KSTR, k0, t);
            ldtile(bb + 1 * TB, Al, bm * 128, KSTR, k0, t);
            ldtile(bb + 2 * TB, Bh, bn * 128, Ktot, k0, t);
            ldtile(bb + 3 * TB, Bl, bn * 128, Ktot, k0, t);
            asm volatile("cp.async.commit_group;");
            asm volatile("cp.async.wait_group 1;");
        } else {
            asm volatile("cp.async.wait_group 0;");
        }
        __syncthreads();
        u32 base = sb + (c & 1) * 4 * TB;
        u32 aH = base, aL = base + TB, bH = base + 2 * TB, bL = base + 3 * TB;
        #pragma unroll
        for (int kk = 0; kk < 32; kk += 16) {
            u32 AH[4][4], AL[4][4], BH[4][2], BL[4][2];
            #pragma unroll
            for (int mt = 0; mt < 4; mt++) {
                u32 ro = (u32)((wm * 64 + mt * 16 + (lane & 15)) * 80 + (kk + (lane >> 4) * 8) * 2);
                ldsm4(AH[mt], aH + ro);
                ldsm4(AL[mt], aL + ro);
            }
            #pragma unroll
            for (int np = 0; np < 2; np++) {
                u32 ro = (u32)((wn * 32 + np * 16 + ((lane >> 4) * 8) + (lane & 7)) * 80
                               + (kk + ((lane >> 3) & 1) * 8) * 2);
                u32 r[4];
                ldsm4(r, bH + ro);
                BH[2 * np][0] = r[0]; BH[2 * np][1] = r[1];
                BH[2 * np + 1][0] = r[2]; BH[2 * np + 1][1] = r[3];
                ldsm4(r, bL + ro);
                BL[2 * np][0] = r[0]; BL[2 * np][1] = r[1];
                BL[2 * np + 1][0] = r[2]; BL[2 * np + 1][1] = r[3];
            }
            #pragma unroll
            for (int mt = 0; mt < 4; mt++)
                #pragma unroll
                for (int nt = 0; nt < 4; nt++) {
                    mma16816(acc[mt][nt], AH[mt], BH[nt]);
                    mma16816(acc[mt][nt], AH[mt], BL[nt]);
                    mma16816(acc[mt][nt], AL[mt], BH[nt]);
                }
        }
        __syncthreads();
    }

    #pragma unroll
    for (int mt = 0; mt < 4; mt++) {
        int rl0 = wm * 64 + mt * 16 + (lane >> 2);
        #pragma unroll
        for (int nt = 0; nt < 4; nt++) {
            int cl = wn * 32 + nt * 8 + (lane & 3) * 2;
            int col = bn * 128 + cl;
            float b0 = (col < Nbias) ? bias[col] : 0.f;
            float b1 = (col + 1 < Nbias) ? bias[col + 1] : 0.f;
            #pragma unroll
            for (int h = 0; h < 2; h++) {
                int row = bm * 128 + rl0 + h * 8;
                float v0 = fmaxf(acc[mt][nt][2 * h + 0] + b0, 0.f);
                float v1 = fmaxf(acc[mt][nt][2 * h + 1] + b1, 0.f);
                *(float2*)(O + (size_t)row * Nstr + col) = make_float2(v0, v1);
                if (Sh) {
                    bf16 h0, l0, h1, l1;
                    splt(v0, h0, l0); splt(v1, h1, l1);
                    __nv_bfloat162 ph; ph.x = h0; ph.y = h1;
                    __nv_bfloat162 pl; pl.x = l0; pl.y = l1;
                    *(__nv_bfloat162*)(Sh + (size_t)row * KSTR + col) = ph;
                    *(__nv_bfloat162*)(Sl + (size_t)row * KSTR + col) = pl;
                }
            }
        }
    }
}

// ---------------- mean pool ----------------------------------------------------
__global__ void pool_kernel(const float* __restrict__ h3, float* __restrict__ out) {
    int b = blockIdx.x;
    int chunk = blockIdx.y;
    int t = threadIdx.x;
    if (t >= 125) return;
    int o = chunk * 125 + t;
    const float* p = h3 + (size_t)(b * 512) * CLSP + o;
    float s = 0.f;
    for (int r = 0; r < 512; r++) s += p[(size_t)r * CLSP];
    out[b * CLS + o] = s * (1.0f / 512.0f);
}

// ---------------- launch --------------------------------------------------------
extern "C" void kernel_launch(void* const* d_in, const int* in_sizes, int n_in,
                              void* d_out, int out_size) {
    const float* x   = (const float*)d_in[0];
    const float* wl0 = (const float*)d_in[1];
    const float* bl0 = (const float*)d_in[2];
    const float* wr0 = (const float*)d_in[3];
    const float* wl1 = (const float*)d_in[4];
    const float* bl1 = (const float*)d_in[5];
    const float* wr1 = (const float*)d_in[6];
    const float* wl2 = (const float*)d_in[7];
    const float* bl2 = (const float*)d_in[8];
    const float* wr2 = (const float*)d_in[9];
    float* out = (float*)d_out;

    bf16 *c0h, *c0l, *c1h, *c1l, *w0h, *w0l, *w1h, *w1l, *w2h, *w2l;
    float *h1, *h2, *h3;
    cudaGetSymbolAddress((void**)&c0h, g_c0h);
    cudaGetSymbolAddress((void**)&c0l, g_c0l);
    cudaGetSymbolAddress((void**)&c1h, g_c1h);
    cudaGetSymbolAddress((void**)&c1l, g_c1l);
    cudaGetSymbolAddress((void**)&w0h, g_w0h);
    cudaGetSymbolAddress((void**)&w0l, g_w0l);
    cudaGetSymbolAddress((void**)&w1h, g_w1h);
    cudaGetSymbolAddress((void**)&w1l, g_w1l);
    cudaGetSymbolAddress((void**)&w2h, g_w2h);
    cudaGetSymbolAddress((void**)&w2l, g_w2l);
    cudaGetSymbolAddress((void**)&h1, g_h1);
    cudaGetSymbolAddress((void**)&h2, g_h2);
    cudaGetSymbolAddress((void**)&h3, g_h3);

    static int smem_set = 0;
    cudaFuncSetAttribute(dist_mma, cudaFuncAttributeMaxDynamicSharedMemorySize, 82944);
    cudaFuncSetAttribute(sage_mma, cudaFuncAttributeMaxDynamicSharedMemorySize, 82944);
    (void)smem_set;

    sq_kernel<<<NN / 8, 256>>>(x);
    xsplit_kernel<<<(NN * FEA + 255) / 256, 256>>>(x);
    wt_build<<<(256 * 384 + 255) / 256, 256>>>(wl0, wr0, FEA, HID, 256, w0h, w0l);
    wt_build<<<(256 * 512 + 255) / 256, 256>>>(wl1, wr1, HID, HID, 256, w1h, w1l);
    wt_build<<<(1024 * 512 + 255) / 256, 256>>>(wl2, wr2, HID, CLS, 1024, w2h, w2l);

    dist_mma<<<dim3(64, 64), 256, 81920>>>(c0h + 192, c0l + 192);
    topk_kernel<<<NN, 256>>>();

    // layer 0: A_cat0 = [agg(x) | x], K=384
    gather_split<<<NN / 4, dim3(FEA / 4, 4)>>>(x, FEA, c0h, c0l);
    sage_mma<<<dim3(2, 64), 256, 81920>>>(c0h, c0l, 384, w0h, w0l, bl0, HID,
                                          h1, HID, c1h + 256, c1l + 256);
    // layer 1: A_cat1 = [agg(h1) | h1], K=512
    gather_split<<<NN / 4, dim3(HID / 4, 4)>>>(h1, HID, c1h, c1l);
    sage_mma<<<dim3(2, 64), 256, 81920>>>(c1h, c1l, 512, w1h, w1l, bl1, HID,
                                          h2, HID, c0h + 256, c0l + 256);
    // layer 2: A_cat0 = [agg(h2) | h2], K=512, N padded to 1024
    gather_split<<<NN / 4, dim3(HID / 4, 4)>>>(h2, HID, c0h, c0l);
    sage_mma<<<dim3(8, 64), 256, 81920>>>(c0h, c0l, 512, w2h, w2l, bl2, CLS,
                                          h3, CLSP, (bf16*)nullptr, (bf16*)nullptr);

    pool_kernel<<<dim3(16, 8), 128>>>(h3, out);
}

// round 4
// speedup vs baseline: 2.0876x; 1.4484x over previous
#include <cuda_runtime.h>
#include <cuda_bf16.h>
#include <cuda_fp16.h>
#include <cfloat>

#define NN   8192
#define FEA  192
#define HID  256
#define CLS  1000
#define CLSP 1024
#define KNB  9
#define NCAND 24
#define KSTR 512

typedef unsigned int u32;
typedef unsigned short u16;
typedef unsigned long long u64;
typedef __nv_bfloat16 bf16;

// ---------------- scratch ----------------------------------------------------
__device__ float g_sq[NN];
__device__ __half g_Dh[(long long)NN * NN];        // 128 MB approx distances
__device__ int   g_idx[NN * KNB];
__device__ bf16  g_c0h[NN * KSTR], g_c0l[NN * KSTR];
__device__ bf16  g_c1h[NN * KSTR], g_c1l[NN * KSTR];
__device__ bf16  g_w0h[256 * 384],  g_w0l[256 * 384];
__device__ bf16  g_w1h[256 * 512],  g_w1l[256 * 512];
__device__ bf16  g_w2h[1024 * 512], g_w2l[1024 * 512];
__device__ float g_h1[NN * HID];
__device__ float g_h2[NN * HID];
__device__ float g_h3[NN * CLSP];

// ---------------- helpers ----------------------------------------------------
__device__ __forceinline__ u32 s2u(const void* p) {
    u32 a;
    asm("{.reg .u64 t; cvta.to.shared.u64 t, %1; cvt.u32.u64 %0, t;}" : "=r"(a) : "l"(p));
    return a;
}
__device__ __forceinline__ void cpa16(u32 dst, const void* src) {
    asm volatile("cp.async.cg.shared.global [%0], [%1], 16;" :: "r"(dst), "l"(src));
}
__device__ __forceinline__ void ldsm4(u32* r, u32 addr) {
    asm volatile("ldmatrix.sync.aligned.m8n8.x4.shared.b16 {%0,%1,%2,%3}, [%4];"
        : "=r"(r[0]), "=r"(r[1]), "=r"(r[2]), "=r"(r[3]) : "r"(addr));
}
__device__ __forceinline__ void mma16816(float* c, const u32* a, const u32* b) {
    asm volatile("mma.sync.aligned.m16n8k16.row.col.f32.bf16.bf16.f32 "
        "{%0,%1,%2,%3},{%4,%5,%6,%7},{%8,%9},{%0,%1,%2,%3};"
        : "+f"(c[0]), "+f"(c[1]), "+f"(c[2]), "+f"(c[3])
        : "r"(a[0]), "r"(a[1]), "r"(a[2]), "r"(a[3]), "r"(b[0]), "r"(b[1]));
}
__device__ __forceinline__ void splt(float v, bf16& h, bf16& l) {
    h = __float2bfloat16_rn(v);
    l = __float2bfloat16_rn(v - __bfloat162float(h));
}

// tile loader: [128 rows x 32 k] bf16 into smem (row stride 40 bf16 = 80B)
__device__ __forceinline__ void ldtile(u32 dstb, const bf16* g, int row0, int ld, int k0, int t) {
    #pragma unroll
    for (int q = 0; q < 2; q++) {
        int id = t * 2 + q;
        int row = id >> 2, kq = id & 3;
        cpa16(dstb + row * 80 + kq * 16, g + (size_t)(row0 + row) * ld + k0 + kq * 8);
    }
}

#define TB 10240   // one tile: 128*40*2 bytes

// ---------------- small kernels ----------------------------------------------
__global__ void sq_kernel(const float* __restrict__ x) {
    int warp = (blockIdx.x * blockDim.x + threadIdx.x) >> 5;
    int lane = threadIdx.x & 31;
    if (warp >= NN) return;
    const float* r = x + (size_t)warp * FEA;
    float s = 0.f;
    for (int c = lane; c < FEA; c += 32) { float v = r[c]; s += v * v; }
    #pragma unroll
    for (int o = 16; o; o >>= 1) s += __shfl_xor_sync(0xffffffffu, s, o);
    if (lane == 0) g_sq[warp] = s;
}

__global__ void xsplit_kernel(const float* __restrict__ x) {
    int i = blockIdx.x * 256 + threadIdx.x;
    if (i >= NN * FEA) return;
    int r = i / FEA, c = i % FEA;
    bf16 h, l; splt(x[i], h, l);
    g_c0h[(size_t)r * KSTR + 192 + c] = h;
    g_c0l[(size_t)r * KSTR + 192 + c] = l;
}

__global__ void wt_build(const float* __restrict__ Wl, const float* __restrict__ Wr,
                         int K1, int Nn, int Npad, bf16* __restrict__ WTh, bf16* __restrict__ WTl) {
    int Ktot = 2 * K1;
    int idx = blockIdx.x * 256 + threadIdx.x;
    if (idx >= Npad * Ktot) return;
    int n = idx / Ktot, k = idx % Ktot;
    float v = 0.f;
    if (n < Nn) v = (k < K1) ? Wl[(size_t)k * Nn + n] : Wr[(size_t)(k - K1) * Nn + n];
    bf16 h, l; splt(v, h, l);
    WTh[idx] = h; WTl[idx] = l;
}

// ---------------- approximate distance GEMM (bf16x1, fp16 out) ----------------
__global__ __launch_bounds__(256, 1) void dist_half(const bf16* __restrict__ Xh) {
    int bj = blockIdx.x, bi = blockIdx.y;
    if (bi > bj) return;
    extern __shared__ __align__(16) char smem[];
    u32 sb = s2u(smem);
    int t = threadIdx.x, lane = t & 31, warp = t >> 5;
    int wm = warp & 1, wn = warp >> 1;

    float acc[4][4][4] = {};

    const int NC = FEA / 32;   // 6
    ldtile(sb + 0 * TB, Xh, bi * 128, KSTR, 0, t);
    ldtile(sb + 1 * TB, Xh, bj * 128, KSTR, 0, t);
    asm volatile("cp.async.commit_group;");

    for (int c = 0; c < NC; c++) {
        if (c + 1 < NC) {
            u32 bb = sb + ((c + 1) & 1) * 2 * TB;
            int k0 = (c + 1) * 32;
            ldtile(bb + 0 * TB, Xh, bi * 128, KSTR, k0, t);
            ldtile(bb + 1 * TB, Xh, bj * 128, KSTR, k0, t);
            asm volatile("cp.async.commit_group;");
            asm volatile("cp.async.wait_group 1;");
        } else {
            asm volatile("cp.async.wait_group 0;");
        }
        __syncthreads();
        u32 base = sb + (c & 1) * 2 * TB;
        u32 aH = base, bH = base + TB;
        #pragma unroll
        for (int kk = 0; kk < 32; kk += 16) {
            u32 AH[4][4], BH[4][2];
            #pragma unroll
            for (int mt = 0; mt < 4; mt++) {
                u32 ro = (u32)((wm * 64 + mt * 16 + (lane & 15)) * 80 + (kk + (lane >> 4) * 8) * 2);
                ldsm4(AH[mt], aH + ro);
            }
            #pragma unroll
            for (int np = 0; np < 2; np++) {
                u32 ro = (u32)((wn * 32 + np * 16 + ((lane >> 4) * 8) + (lane & 7)) * 80
                               + (kk + ((lane >> 3) & 1) * 8) * 2);
                u32 r[4];
                ldsm4(r, bH + ro);
                BH[2 * np][0] = r[0]; BH[2 * np][1] = r[1];
                BH[2 * np + 1][0] = r[2]; BH[2 * np + 1][1] = r[3];
            }
            #pragma unroll
            for (int mt = 0; mt < 4; mt++)
                #pragma unroll
                for (int nt = 0; nt < 4; nt++)
                    mma16816(acc[mt][nt], AH[mt], BH[nt]);
        }
        __syncthreads();
    }

    // epilogue: stage both tiles as fp16 in smem, write coalesced
    u16* sD = (u16*)smem;            // [128][136]
    u16* sT = sD + 128 * 136;        // transposed
    bool diag = (bi == bj);
    #pragma unroll
    for (int mt = 0; mt < 4; mt++) {
        int rl0 = wm * 64 + mt * 16 + (lane >> 2);
        #pragma unroll
        for (int nt = 0; nt < 4; nt++) {
            int cl = wn * 32 + nt * 8 + (lane & 3) * 2;
            float sqc0 = g_sq[bj * 128 + cl], sqc1 = g_sq[bj * 128 + cl + 1];
            #pragma unroll
            for (int h = 0; h < 2; h++) {
                int rl = rl0 + h * 8;
                float sr = g_sq[bi * 128 + rl];
                float d0 = sr + sqc0 - 2.f * acc[mt][nt][2 * h + 0];
                float d1 = sr + sqc1 - 2.f * acc[mt][nt][2 * h + 1];
                u16 b0 = __half_as_ushort(__float2half_rn(d0));
                u16 b1 = __half_as_ushort(__float2half_rn(d1));
                sD[rl * 136 + cl] = b0;
                sD[rl * 136 + cl + 1] = b1;
                if (!diag) {
                    sT[cl * 136 + rl] = b0;
                    sT[(cl + 1) * 136 + rl] = b1;
                }
            }
        }
    }
    __syncthreads();
    u16* gD = (u16*)g_Dh;
    for (int e = t; e < 128 * 16; e += 256) {
        int r = e >> 4, c8 = (e & 15) * 8;
        uint4 v = *(uint4*)&sD[r * 136 + c8];
        *(uint4*)(gD + (size_t)(bi * 128 + r) * NN + bj * 128 + c8) = v;
    }
    if (!diag) {
        for (int e = t; e < 128 * 16; e += 256) {
            int r = e >> 4, c8 = (e & 15) * 8;
            uint4 v = *(uint4*)&sT[r * 136 + c8];
            *(uint4*)(gD + (size_t)(bj * 128 + r) * NN + bi * 128 + c8) = v;
        }
    }
}

// ---------------- top-24 candidates + exact fp32 refine to top-9 --------------
__global__ __launch_bounds__(256) void topk_refine(const float* __restrict__ x) {
    int i = blockIdx.x;
    int t = threadIdx.x, lane = t & 31, wid = t >> 5;
    __shared__ u16 skey[NN];
    __shared__ u32 wmin[8];
    __shared__ u32 bcast;
    __shared__ int cand[NCAND];
    __shared__ float cdist[NCAND];
    __shared__ float xi[FEA];

    // load my 32-value segment, build order-preserving u16 keys
    const u16* row = (const u16*)(g_Dh + (size_t)i * NN);
    int j0 = t * 32;
    u32 mylm = 0xFFFFFFFFu;
    #pragma unroll
    for (int q = 0; q < 4; q++) {
        uint4 v = __ldg((const uint4*)(row + j0 + q * 8));
        u32 w[4] = {v.x, v.y, v.z, v.w};
        #pragma unroll
        for (int p = 0; p < 4; p++) {
            #pragma unroll
            for (int hh = 0; hh < 2; hh++) {
                u16 hb = (u16)(w[p] >> (16 * hh));
                u16 key = (u16)(hb ^ ((hb & 0x8000) ? 0xFFFFu : 0x8000u));
                int j = j0 + q * 8 + p * 2 + hh;
                skey[j] = key;
                u32 pk = ((u32)key << 16) | (u32)j;
                mylm = min(mylm, pk);
            }
        }
    }

    // 24 rounds of block argmin with removal
    for (int r = 0; r < NCAND; r++) {
        u32 v = mylm;
        #pragma unroll
        for (int o = 16; o; o >>= 1) v = min(v, __shfl_xor_sync(0xffffffffu, v, o));
        if (lane == 0) wmin[wid] = v;
        __syncthreads();
        if (t < 8) {
            u32 u = wmin[t];
            #pragma unroll
            for (int o = 4; o; o >>= 1) u = min(u, __shfl_xor_sync(0xffu, u, o));
            if (t == 0) { bcast = u; cand[r] = (int)(u & 0xFFFFu); }
        }
        __syncthreads();
        int jstar = (int)(bcast & 0xFFFFu);
        if ((jstar >> 5) == t) {
            skey[jstar] = 0xFFFFu;
            u32 nm = 0xFFFFFFFFu;
            #pragma unroll
            for (int q = 0; q < 32; q++) {
                int j = j0 + q;
                nm = min(nm, ((u32)skey[j] << 16) | (u32)j);
            }
            mylm = nm;
        }
        __syncthreads();
    }

    // exact fp32 refine of the 24 candidates
    for (int d = t; d < FEA; d += 256) xi[d] = __ldg(x + (size_t)i * FEA + d);
    __syncthreads();
    #pragma unroll
    for (int q = 0; q < 3; q++) {
        int c = wid + q * 8;
        int j = cand[c];
        const float* xj = x + (size_t)j * FEA;
        float s = 0.f;
        #pragma unroll
        for (int d = lane; d < FEA; d += 32) s = fmaf(xi[d], __ldg(xj + d), s);
        #pragma unroll
        for (int o = 16; o; o >>= 1) s += __shfl_xor_sync(0xffffffffu, s, o);
        if (lane == 0) cdist[c] = g_sq[i] + g_sq[j] - 2.f * s;
    }
    __syncthreads();
    if (t == 0) {
        u64 keys[NCAND];
        #pragma unroll
        for (int c = 0; c < NCAND; c++) {
            u32 b = __float_as_uint(cdist[c]);
            b ^= (b & 0x80000000u) ? 0xFFFFFFFFu : 0x80000000u;
            keys[c] = ((u64)b << 32) | (u32)cand[c];
        }
        #pragma unroll
        for (int r = 0; r < KNB; r++) {
            u64 best = keys[0]; int bs = 0;
            #pragma unroll
            for (int c = 1; c < NCAND; c++)
                if (keys[c] < best) { best = keys[c]; bs = c; }
            g_idx[i * KNB + r] = (int)(best & 0xFFFFFFFFull);
            keys[bs] = ~0ull;
        }
    }
}

// ---------------- gather + mean -> bf16 hi/lo split ---------------------------
__global__ void gather_split(const float* __restrict__ h, int C,
                             bf16* __restrict__ oh, bf16* __restrict__ ol) {
    int row = blockIdx.x * 4 + threadIdx.y;
    int c4 = threadIdx.x * 4;
    const int* idp = g_idx + row * KNB;
    float4 s = make_float4(0.f, 0.f, 0.f, 0.f);
    #pragma unroll
    for (int j = 0; j < KNB; j++) {
        float4 v = __ldg((const float4*)(h + (size_t)idp[j] * C + c4));
        s.x += v.x; s.y += v.y; s.z += v.z; s.w += v.w;
    }
    const float inv = 1.0f / 9.0f;
    float vv[4] = {s.x * inv, s.y * inv, s.z * inv, s.w * inv};
    size_t off = (size_t)row * KSTR + c4;
    #pragma unroll
    for (int e = 0; e < 4; e += 2) {
        bf16 h0, l0, h1, l1;
        splt(vv[e], h0, l0); splt(vv[e + 1], h1, l1);
        __nv_bfloat162 ph; ph.x = h0; ph.y = h1;
        __nv_bfloat162 pl; pl.x = l0; pl.y = l1;
        *(__nv_bfloat162*)(oh + off + e) = ph;
        *(__nv_bfloat162*)(ol + off + e) = pl;
    }
}

// ---------------- SAGE dual-GEMM: relu([agg|h]@[Wl;Wr] + b) -------------------
__global__ __launch_bounds__(256, 1) void sage_mma(
    const bf16* __restrict__ Ah, const bf16* __restrict__ Al, int Ktot,
    const bf16* __restrict__ Bh, const bf16* __restrict__ Bl,
    const float* __restrict__ bias, int Nbias,
    float* __restrict__ O, int Nstr,
    bf16* __restrict__ Sh, bf16* __restrict__ Sl)
{
    int bn = blockIdx.x, bm = blockIdx.y;
    extern __shared__ __align__(16) char smem[];
    u32 sb = s2u(smem);
    int t = threadIdx.x, lane = t & 31, warp = t >> 5;
    int wm = warp & 1, wn = warp >> 1;

    float acc[4][4][4] = {};

    int nc = Ktot / 32;
    ldtile(sb + 0 * TB, Ah, bm * 128, KSTR, 0, t);
    ldtile(sb + 1 * TB, Al, bm * 128, KSTR, 0, t);
    ldtile(sb + 2 * TB, Bh, bn * 128, Ktot, 0, t);
    ldtile(sb + 3 * TB, Bl, bn * 128, Ktot, 0, t);
    asm volatile("cp.async.commit_group;");

    for (int c = 0; c < nc; c++) {
        if (c + 1 < nc) {
            u32 bb = sb + ((c + 1) & 1) * 4 * TB;
            int k0 = (c + 1) * 32;
            ldtile(bb + 0 * TB, Ah, bm * 128, KSTR, k0, t);
            ldtile(bb + 1 * TB, Al, bm * 128, KSTR, k0, t);
            ldtile(bb + 2 * TB, Bh, bn * 128, Ktot, k0, t);
            ldtile(bb + 3 * TB, Bl, bn * 128, Ktot, k0, t);
            asm volatile("cp.async.commit_group;");
            asm volatile("cp.async.wait_group 1;");
        } else {
            asm volatile("cp.async.wait_group 0;");
        }
        __syncthreads();
        u32 base = sb + (c & 1) * 4 * TB;
        u32 aH = base, aL = base + TB, bH = base + 2 * TB, bL = base + 3 * TB;
        #pragma unroll
        for (int kk = 0; kk < 32; kk += 16) {
            u32 AH[4][4], AL[4][4], BH[4][2], BL[4][2];
            #pragma unroll
            for (int mt = 0; mt < 4; mt++) {
                u32 ro = (u32)((wm * 64 + mt * 16 + (lane & 15)) * 80 + (kk + (lane >> 4) * 8) * 2);
                ldsm4(AH[mt], aH + ro);
                ldsm4(AL[mt], aL + ro);
            }
            #pragma unroll
            for (int np = 0; np < 2; np++) {
                u32 ro = (u32)((wn * 32 + np * 16 + ((lane >> 4) * 8) + (lane & 7)) * 80
                               + (kk + ((lane >> 3) & 1) * 8) * 2);
                u32 r[4];
                ldsm4(r, bH + ro);
                BH[2 * np][0] = r[0]; BH[2 * np][1] = r[1];
                BH[2 * np + 1][0] = r[2]; BH[2 * np + 1][1] = r[3];
                ldsm4(r, bL + ro);
                BL[2 * np][0] = r[0]; BL[2 * np][1] = r[1];
                BL[2 * np + 1][0] = r[2]; BL[2 * np + 1][1] = r[3];
            }
            #pragma unroll
            for (int mt = 0; mt < 4; mt++)
                #pragma unroll
                for (int nt = 0; nt < 4; nt++) {
                    mma16816(acc[mt][nt], AH[mt], BH[nt]);
                    mma16816(acc[mt][nt], AH[mt], BL[nt]);
                    mma16816(acc[mt][nt], AL[mt], BH[nt]);
                }
        }
        __syncthreads();
    }

    #pragma unroll
    for (int mt = 0; mt < 4; mt++) {
        int rl0 = wm * 64 + mt * 16 + (lane >> 2);
        #pragma unroll
        for (int nt = 0; nt < 4; nt++) {
            int cl = wn * 32 + nt * 8 + (lane & 3) * 2;
            int col = bn * 128 + cl;
            float b0 = (col < Nbias) ? bias[col] : 0.f;
            float b1 = (col + 1 < Nbias) ? bias[col + 1] : 0.f;
            #pragma unroll
            for (int h = 0; h < 2; h++) {
                int row = bm * 128 + rl0 + h * 8;
                float v0 = fmaxf(acc[mt][nt][2 * h + 0] + b0, 0.f);
                float v1 = fmaxf(acc[mt][nt][2 * h + 1] + b1, 0.f);
                *(float2*)(O + (size_t)row * Nstr + col) = make_float2(v0, v1);
                if (Sh) {
                    bf16 h0, l0, h1, l1;
                    splt(v0, h0, l0); splt(v1, h1, l1);
                    __nv_bfloat162 ph; ph.x = h0; ph.y = h1;
                    __nv_bfloat162 pl; pl.x = l0; pl.y = l1;
                    *(__nv_bfloat162*)(Sh + (size_t)row * KSTR + col) = ph;
                    *(__nv_bfloat162*)(Sl + (size_t)row * KSTR + col) = pl;
                }
            }
        }
    }
}

// ---------------- mean pool ----------------------------------------------------
__global__ void pool_kernel(const float* __restrict__ h3, float* __restrict__ out) {
    int b = blockIdx.x;
    int chunk = blockIdx.y;
    int t = threadIdx.x;
    if (t >= 125) return;
    int o = chunk * 125 + t;
    const float* p = h3 + (size_t)(b * 512) * CLSP + o;
    float s = 0.f;
    for (int r = 0; r < 512; r++) s += p[(size_t)r * CLSP];
    out[b * CLS + o] = s * (1.0f / 512.0f);
}

// ---------------- launch --------------------------------------------------------
#define DIST_SMEM (128 * 136 * 2 * 2)   // 69632 (epilogue stage dominates)
#define SAGE_SMEM (8 * TB)              // 81920

extern "C" void kernel_launch(void* const* d_in, const int* in_sizes, int n_in,
                              void* d_out, int out_size) {
    const float* x   = (const float*)d_in[0];
    const float* wl0 = (const float*)d_in[1];
    const float* bl0 = (const float*)d_in[2];
    const float* wr0 = (const float*)d_in[3];
    const float* wl1 = (const float*)d_in[4];
    const float* bl1 = (const float*)d_in[5];
    const float* wr1 = (const float*)d_in[6];
    const float* wl2 = (const float*)d_in[7];
    const float* bl2 = (const float*)d_in[8];
    const float* wr2 = (const float*)d_in[9];
    float* out = (float*)d_out;

    bf16 *c0h, *c0l, *c1h, *c1l, *w0h, *w0l, *w1h, *w1l, *w2h, *w2l;
    float *h1, *h2, *h3;
    cudaGetSymbolAddress((void**)&c0h, g_c0h);
    cudaGetSymbolAddress((void**)&c0l, g_c0l);
    cudaGetSymbolAddress((void**)&c1h, g_c1h);
    cudaGetSymbolAddress((void**)&c1l, g_c1l);
    cudaGetSymbolAddress((void**)&w0h, g_w0h);
    cudaGetSymbolAddress((void**)&w0l, g_w0l);
    cudaGetSymbolAddress((void**)&w1h, g_w1h);
    cudaGetSymbolAddress((void**)&w1l, g_w1l);
    cudaGetSymbolAddress((void**)&w2h, g_w2h);
    cudaGetSymbolAddress((void**)&w2l, g_w2l);
    cudaGetSymbolAddress((void**)&h1, g_h1);
    cudaGetSymbolAddress((void**)&h2, g_h2);
    cudaGetSymbolAddress((void**)&h3, g_h3);

    cudaFuncSetAttribute(dist_half, cudaFuncAttributeMaxDynamicSharedMemorySize, DIST_SMEM);
    cudaFuncSetAttribute(sage_mma, cudaFuncAttributeMaxDynamicSharedMemorySize, SAGE_SMEM);

    sq_kernel<<<NN / 8, 256>>>(x);
    xsplit_kernel<<<(NN * FEA + 255) / 256, 256>>>(x);
    wt_build<<<(256 * 384 + 255) / 256, 256>>>(wl0, wr0, FEA, HID, 256, w0h, w0l);
    wt_build<<<(256 * 512 + 255) / 256, 256>>>(wl1, wr1, HID, HID, 256, w1h, w1l);
    wt_build<<<(1024 * 512 + 255) / 256, 256>>>(wl2, wr2, HID, CLS, 1024, w2h, w2l);

    dist_half<<<dim3(64, 64), 256, DIST_SMEM>>>(c0h + 192);
    topk_refine<<<NN, 256>>>(x);

    // layer 0: [agg(x) | x], K=384
    gather_split<<<NN / 4, dim3(FEA / 4, 4)>>>(x, FEA, c0h, c0l);
    sage_mma<<<dim3(2, 64), 256, SAGE_SMEM>>>(c0h, c0l, 384, w0h, w0l, bl0, HID,
                                              h1, HID, c1h + 256, c1l + 256);
    // layer 1: [agg(h1) | h1], K=512
    gather_split<<<NN / 4, dim3(HID / 4, 4)>>>(h1, HID, c1h, c1l);
    sage_mma<<<dim3(2, 64), 256, SAGE_SMEM>>>(c1h, c1l, 512, w1h, w1l, bl1, HID,
                                              h2, HID, c0h + 256, c0l + 256);
    // layer 2: [agg(h2) | h2], K=512, N padded 1024
    gather_split<<<NN / 4, dim3(HID / 4, 4)>>>(h2, HID, c0h, c0l);
    sage_mma<<<dim3(8, 64), 256, SAGE_SMEM>>>(c0h, c0l, 512, w2h, w2l, bl2, CLS,
                                              h3, CLSP, (bf16*)nullptr, (bf16*)nullptr);

    pool_kernel<<<dim3(16, 8), 128>>>(h3, out);
}

// round 5
// speedup vs baseline: 2.7075x; 1.2970x over previous
#include <cuda_runtime.h>
#include <cuda_fp16.h>
#include <cfloat>

#define NN   8192
#define FEA  192
#define HID  256
#define CLS  1000
#define CLSP 1024
#define KNB  9
#define NCAND 16
#define KSTR 512

typedef unsigned int u32;
typedef unsigned short u16;
typedef unsigned long long u64;
typedef __half f16;

// ---------------- scratch ----------------------------------------------------
__device__ float g_sq[NN];
__device__ __half g_Dh[(long long)NN * NN];        // 128 MB approx distances
__device__ int   g_idx[NN * KNB];
__device__ f16   g_c0h[NN * KSTR];                 // activation cat buffer 0 (hi only)
__device__ f16   g_c1h[NN * KSTR];                 // activation cat buffer 1
__device__ f16   g_w0h[256 * 384],  g_w0l[256 * 384];
__device__ f16   g_w1h[256 * 512],  g_w1l[256 * 512];
__device__ f16   g_w2h[1024 * 512], g_w2l[1024 * 512];
__device__ float g_h1[NN * HID];
__device__ float g_h2[NN * HID];
__device__ float g_h3[NN * CLSP];

// ---------------- helpers ----------------------------------------------------
__device__ __forceinline__ u32 s2u(const void* p) {
    u32 a;
    asm("{.reg .u64 t; cvta.to.shared.u64 t, %1; cvt.u32.u64 %0, t;}" : "=r"(a) : "l"(p));
    return a;
}
__device__ __forceinline__ void cpa16(u32 dst, const void* src) {
    asm volatile("cp.async.cg.shared.global [%0], [%1], 16;" :: "r"(dst), "l"(src));
}
__device__ __forceinline__ void ldsm4(u32* r, u32 addr) {
    asm volatile("ldmatrix.sync.aligned.m8n8.x4.shared.b16 {%0,%1,%2,%3}, [%4];"
        : "=r"(r[0]), "=r"(r[1]), "=r"(r[2]), "=r"(r[3]) : "r"(addr));
}
__device__ __forceinline__ void mma16816(float* c, const u32* a, const u32* b) {
    asm volatile("mma.sync.aligned.m16n8k16.row.col.f32.f16.f16.f32 "
        "{%0,%1,%2,%3},{%4,%5,%6,%7},{%8,%9},{%0,%1,%2,%3};"
        : "+f"(c[0]), "+f"(c[1]), "+f"(c[2]), "+f"(c[3])
        : "r"(a[0]), "r"(a[1]), "r"(a[2]), "r"(a[3]), "r"(b[0]), "r"(b[1]));
}
__device__ __forceinline__ void spltw(float v, f16& h, f16& l) {
    h = __float2half_rn(v);
    l = __float2half_rn(v - __half2float(h));
}

// tile loader: [128 rows x 32 k] fp16 into smem (row stride 40 halfs = 80B)
__device__ __forceinline__ void ldtile(u32 dstb, const f16* g, int row0, int ld, int k0, int t) {
    #pragma unroll
    for (int q = 0; q < 2; q++) {
        int id = t * 2 + q;
        int row = id >> 2, kq = id & 3;
        cpa16(dstb + row * 80 + kq * 16, g + (size_t)(row0 + row) * ld + k0 + kq * 8);
    }
}

#define TB 10240   // one tile: 128*40*2 bytes

// ---------------- small kernels ----------------------------------------------
__global__ void sq_kernel(const float* __restrict__ x) {
    int warp = (blockIdx.x * blockDim.x + threadIdx.x) >> 5;
    int lane = threadIdx.x & 31;
    if (warp >= NN) return;
    const float* r = x + (size_t)warp * FEA;
    float s = 0.f;
    for (int c = lane; c < FEA; c += 32) { float v = r[c]; s += v * v; }
    #pragma unroll
    for (int o = 16; o; o >>= 1) s += __shfl_xor_sync(0xffffffffu, s, o);
    if (lane == 0) g_sq[warp] = s;
}

__global__ void xsplit_kernel(const float* __restrict__ x) {
    int i = blockIdx.x * 256 + threadIdx.x;
    if (i >= NN * FEA) return;
    int r = i / FEA, c = i % FEA;
    g_c0h[(size_t)r * KSTR + 192 + c] = __float2half_rn(x[i]);
}

// merged builder for layers 0 and 1 (blockIdx.y selects layer)
__global__ void wt_build01(const float* __restrict__ Wl0, const float* __restrict__ Wr0,
                           const float* __restrict__ Wl1, const float* __restrict__ Wr1) {
    int layer = blockIdx.y;
    const float* Wl = layer ? Wl1 : Wl0;
    const float* Wr = layer ? Wr1 : Wr0;
    f16* WTh = layer ? g_w1h : g_w0h;
    f16* WTl = layer ? g_w1l : g_w0l;
    int K1 = layer ? 256 : 192;
    int Ktot = 2 * K1;
    int total = 256 * Ktot;
    int idx = blockIdx.x * 256 + threadIdx.x;
    if (idx >= total) return;
    int k = idx % Ktot;
    int n = idx / Ktot;
    float v = (k < K1) ? Wl[(size_t)k * HID + n] : Wr[(size_t)(k - K1) * HID + n];
    f16 h, l; spltw(v, h, l);
    WTh[idx] = h; WTl[idx] = l;
}

__global__ void wt_build2(const float* __restrict__ Wl, const float* __restrict__ Wr) {
    int idx = blockIdx.x * 256 + threadIdx.x;
    if (idx >= 1024 * 512) return;
    int n = idx / 512, k = idx % 512;
    float v = 0.f;
    if (n < CLS) v = (k < 256) ? Wl[(size_t)k * CLS + n] : Wr[(size_t)(k - 256) * CLS + n];
    f16 h, l; spltw(v, h, l);
    g_w2h[idx] = h; g_w2l[idx] = l;
}

// ---------------- approximate distance GEMM (fp16x1, fp16 out) ----------------
__global__ __launch_bounds__(256, 1) void dist_half(const f16* __restrict__ Xh) {
    int bj = blockIdx.x, bi = blockIdx.y;
    if (bi > bj) return;
    extern __shared__ __align__(16) char smem[];
    u32 sb = s2u(smem);
    int t = threadIdx.x, lane = t & 31, warp = t >> 5;
    int wm = warp & 1, wn = warp >> 1;

    float acc[4][4][4] = {};

    const int NC = FEA / 32;   // 6
    ldtile(sb + 0 * TB, Xh, bi * 128, KSTR, 0, t);
    ldtile(sb + 1 * TB, Xh, bj * 128, KSTR, 0, t);
    asm volatile("cp.async.commit_group;");

    for (int c = 0; c < NC; c++) {
        if (c + 1 < NC) {
            u32 bb = sb + ((c + 1) & 1) * 2 * TB;
            int k0 = (c + 1) * 32;
            ldtile(bb + 0 * TB, Xh, bi * 128, KSTR, k0, t);
            ldtile(bb + 1 * TB, Xh, bj * 128, KSTR, k0, t);
            asm volatile("cp.async.commit_group;");
            asm volatile("cp.async.wait_group 1;");
        } else {
            asm volatile("cp.async.wait_group 0;");
        }
        __syncthreads();
        u32 base = sb + (c & 1) * 2 * TB;
        u32 aH = base, bH = base + TB;
        #pragma unroll
        for (int kk = 0; kk < 32; kk += 16) {
            u32 AH[4][4], BH[4][2];
            #pragma unroll
            for (int mt = 0; mt < 4; mt++) {
                u32 ro = (u32)((wm * 64 + mt * 16 + (lane & 15)) * 80 + (kk + (lane >> 4) * 8) * 2);
                ldsm4(AH[mt], aH + ro);
            }
            #pragma unroll
            for (int np = 0; np < 2; np++) {
                u32 ro = (u32)((wn * 32 + np * 16 + ((lane >> 4) * 8) + (lane & 7)) * 80
                               + (kk + ((lane >> 3) & 1) * 8) * 2);
                u32 r[4];
                ldsm4(r, bH + ro);
                BH[2 * np][0] = r[0]; BH[2 * np][1] = r[1];
                BH[2 * np + 1][0] = r[2]; BH[2 * np + 1][1] = r[3];
            }
            #pragma unroll
            for (int mt = 0; mt < 4; mt++)
                #pragma unroll
                for (int nt = 0; nt < 4; nt++)
                    mma16816(acc[mt][nt], AH[mt], BH[nt]);
        }
        __syncthreads();
    }

    // epilogue: stage both tiles as fp16 in smem, write coalesced
    u16* sD = (u16*)smem;            // [128][136]
    u16* sT = sD + 128 * 136;        // transposed
    bool diag = (bi == bj);
    #pragma unroll
    for (int mt = 0; mt < 4; mt++) {
        int rl0 = wm * 64 + mt * 16 + (lane >> 2);
        #pragma unroll
        for (int nt = 0; nt < 4; nt++) {
            int cl = wn * 32 + nt * 8 + (lane & 3) * 2;
            float sqc0 = g_sq[bj * 128 + cl], sqc1 = g_sq[bj * 128 + cl + 1];
            #pragma unroll
            for (int h = 0; h < 2; h++) {
                int rl = rl0 + h * 8;
                float sr = g_sq[bi * 128 + rl];
                float d0 = sr + sqc0 - 2.f * acc[mt][nt][2 * h + 0];
                float d1 = sr + sqc1 - 2.f * acc[mt][nt][2 * h + 1];
                u16 b0 = __half_as_ushort(__float2half_rn(d0));
                u16 b1 = __half_as_ushort(__float2half_rn(d1));
                sD[rl * 136 + cl] = b0;
                sD[rl * 136 + cl + 1] = b1;
                if (!diag) {
                    sT[cl * 136 + rl] = b0;
                    sT[(cl + 1) * 136 + rl] = b1;
                }
            }
        }
    }
    __syncthreads();
    u16* gD = (u16*)g_Dh;
    for (int e = t; e < 128 * 16; e += 256) {
        int r = e >> 4, c8 = (e & 15) * 8;
        uint4 v = *(uint4*)&sD[r * 136 + c8];
        *(uint4*)(gD + (size_t)(bi * 128 + r) * NN + bj * 128 + c8) = v;
    }
    if (!diag) {
        for (int e = t; e < 128 * 16; e += 256) {
            int r = e >> 4, c8 = (e & 15) * 8;
            uint4 v = *(uint4*)&sT[r * 136 + c8];
            *(uint4*)(gD + (size_t)(bj * 128 + r) * NN + bi * 128 + c8) = v;
        }
    }
}

// ---------------- top-16 candidates + exact fp32 refine to top-9 --------------
__global__ __launch_bounds__(256) void topk_refine(const float* __restrict__ x) {
    int i = blockIdx.x;
    int t = threadIdx.x, lane = t & 31, wid = t >> 5;
    __shared__ u16 skey[NN];
    __shared__ u32 wmin[8];
    __shared__ u32 bcast;
    __shared__ int cand[NCAND];
    __shared__ float cdist[NCAND];
    __shared__ float xi[FEA];

    // load my 32-value segment, build order-preserving u16 keys
    const u16* row = (const u16*)(g_Dh + (size_t)i * NN);
    int j0 = t * 32;
    u32 mylm = 0xFFFFFFFFu;
    #pragma unroll
    for (int q = 0; q < 4; q++) {
        uint4 v = __ldg((const uint4*)(row + j0 + q * 8));
        u32 w[4] = {v.x, v.y, v.z, v.w};
        #pragma unroll
        for (int p = 0; p < 4; p++) {
            #pragma unroll
            for (int hh = 0; hh < 2; hh++) {
                u16 hb = (u16)(w[p] >> (16 * hh));
                u16 key = (u16)(hb ^ ((hb & 0x8000) ? 0xFFFFu : 0x8000u));
                int j = j0 + q * 8 + p * 2 + hh;
                skey[j] = key;
                u32 pk = ((u32)key << 16) | (u32)j;
                mylm = min(mylm, pk);
            }
        }
    }

    // NCAND rounds of block argmin with removal
    for (int r = 0; r < NCAND; r++) {
        u32 v = mylm;
        #pragma unroll
        for (int o = 16; o; o >>= 1) v = min(v, __shfl_xor_sync(0xffffffffu, v, o));
        if (lane == 0) wmin[wid] = v;
        __syncthreads();
        if (t < 8) {
            u32 u = wmin[t];
            #pragma unroll
            for (int o = 4; o; o >>= 1) u = min(u, __shfl_xor_sync(0xffu, u, o));
            if (t == 0) { bcast = u; cand[r] = (int)(u & 0xFFFFu); }
        }
        __syncthreads();
        int jstar = (int)(bcast & 0xFFFFu);
        if ((jstar >> 5) == t) {
            skey[jstar] = 0xFFFFu;
            u32 nm = 0xFFFFFFFFu;
            #pragma unroll
            for (int q = 0; q < 32; q++) {
                int j = j0 + q;
                nm = min(nm, ((u32)skey[j] << 16) | (u32)j);
            }
            mylm = nm;
        }
        __syncthreads();
    }

    // exact fp32 refine of the candidates
    for (int d = t; d < FEA; d += 256) xi[d] = __ldg(x + (size_t)i * FEA + d);
    __syncthreads();
    #pragma unroll
    for (int q = 0; q < NCAND / 8; q++) {
        int c = wid + q * 8;
        int j = cand[c];
        const float* xj = x + (size_t)j * FEA;
        float s = 0.f;
        #pragma unroll
        for (int d = lane; d < FEA; d += 32) s = fmaf(xi[d], __ldg(xj + d), s);
        #pragma unroll
        for (int o = 16; o; o >>= 1) s += __shfl_xor_sync(0xffffffffu, s, o);
        if (lane == 0) cdist[c] = g_sq[i] + g_sq[j] - 2.f * s;
    }
    __syncthreads();
    if (t == 0) {
        u64 keys[NCAND];
        #pragma unroll
        for (int c = 0; c < NCAND; c++) {
            u32 b = __float_as_uint(cdist[c]);
            b ^= (b & 0x80000000u) ? 0xFFFFFFFFu : 0x80000000u;
            keys[c] = ((u64)b << 32) | (u32)cand[c];
        }
        #pragma unroll
        for (int r = 0; r < KNB; r++) {
            u64 best = keys[0]; int bs = 0;
            #pragma unroll
            for (int c = 1; c < NCAND; c++)
                if (keys[c] < best) { best = keys[c]; bs = c; }
            g_idx[i * KNB + r] = (int)(best & 0xFFFFFFFFull);
            keys[bs] = ~0ull;
        }
    }
}

// ---------------- gather + mean -> fp16 ----------------------------------------
__global__ void gather_split(const float* __restrict__ h, int C, f16* __restrict__ oh) {
    int row = blockIdx.x * 4 + threadIdx.y;
    int c4 = threadIdx.x * 4;
    const int* idp = g_idx + row * KNB;
    float4 s = make_float4(0.f, 0.f, 0.f, 0.f);
    #pragma unroll
    for (int j = 0; j < KNB; j++) {
        float4 v = __ldg((const float4*)(h + (size_t)idp[j] * C + c4));
        s.x += v.x; s.y += v.y; s.z += v.z; s.w += v.w;
    }
    const float inv = 1.0f / 9.0f;
    size_t off = (size_t)row * KSTR + c4;
    __half2 p0; p0.x = __float2half_rn(s.x * inv); p0.y = __float2half_rn(s.y * inv);
    __half2 p1; p1.x = __float2half_rn(s.z * inv); p1.y = __float2half_rn(s.w * inv);
    *(__half2*)(oh + off)     = p0;
    *(__half2*)(oh + off + 2) = p1;
}

// ---------------- SAGE dual-GEMM: relu(A@[Wl;Wr] + b), fp16 2-term -------------
__global__ __launch_bounds__(256, 1) void sage_mma(
    const f16* __restrict__ Ah, int Ktot,
    const f16* __restrict__ Bh, const f16* __restrict__ Bl,
    const float* __restrict__ bias, int Nbias,
    float* __restrict__ O, int Nstr,
    f16* __restrict__ Sh)
{
    int bn = blockIdx.x, bm = blockIdx.y;
    extern __shared__ __align__(16) char smem[];
    u32 sb = s2u(smem);
    int t = threadIdx.x, lane = t & 31, warp = t >> 5;
    int wm = warp & 1, wn = warp >> 1;

    float acc[4][4][4] = {};

    int nc = Ktot / 32;
    ldtile(sb + 0 * TB, Ah, bm * 128, KSTR, 0, t);
    ldtile(sb + 1 * TB, Bh, bn * 128, Ktot, 0, t);
    ldtile(sb + 2 * TB, Bl, bn * 128, Ktot, 0, t);
    asm volatile("cp.async.commit_group;");

    for (int c = 0; c < nc; c++) {
        if (c + 1 < nc) {
            u32 bb = sb + ((c + 1) & 1) * 3 * TB;
            int k0 = (c + 1) * 32;
            ldtile(bb + 0 * TB, Ah, bm * 128, KSTR, k0, t);
            ldtile(bb + 1 * TB, Bh, bn * 128, Ktot, k0, t);
            ldtile(bb + 2 * TB, Bl, bn * 128, Ktot, k0, t);
            asm volatile("cp.async.commit_group;");
            asm volatile("cp.async.wait_group 1;");
        } else {
            asm volatile("cp.async.wait_group 0;");
        }
        __syncthreads();
        u32 base = sb + (c & 1) * 3 * TB;
        u32 aH = base, bH = base + TB, bL = base + 2 * TB;
        #pragma unroll
        for (int kk = 0; kk < 32; kk += 16) {
            u32 AH[4][4], BH[4][2], BL[4][2];
            #pragma unroll
            for (int mt = 0; mt < 4; mt++) {
                u32 ro = (u32)((wm * 64 + mt * 16 + (lane & 15)) * 80 + (kk + (lane >> 4) * 8) * 2);
                ldsm4(AH[mt], aH + ro);
            }
            #pragma unroll
            for (int np = 0; np < 2; np++) {
                u32 ro = (u32)((wn * 32 + np * 16 + ((lane >> 4) * 8) + (lane & 7)) * 80
                               + (kk + ((lane >> 3) & 1) * 8) * 2);
                u32 r[4];
                ldsm4(r, bH + ro);
                BH[2 * np][0] = r[0]; BH[2 * np][1] = r[1];
                BH[2 * np + 1][0] = r[2]; BH[2 * np + 1][1] = r[3];
                ldsm4(r, bL + ro);
                BL[2 * np][0] = r[0]; BL[2 * np][1] = r[1];
                BL[2 * np + 1][0] = r[2]; BL[2 * np + 1][1] = r[3];
            }
            #pragma unroll
            for (int mt = 0; mt < 4; mt++)
                #pragma unroll
                for (int nt = 0; nt < 4; nt++) {
                    mma16816(acc[mt][nt], AH[mt], BH[nt]);
                    mma16816(acc[mt][nt], AH[mt], BL[nt]);
                }
        }
        __syncthreads();
    }

    #pragma unroll
    for (int mt = 0; mt < 4; mt++) {
        int rl0 = wm * 64 + mt * 16 + (lane >> 2);
        #pragma unroll
        for (int nt = 0; nt < 4; nt++) {
            int cl = wn * 32 + nt * 8 + (lane & 3) * 2;
            int col = bn * 128 + cl;
            float b0 = (col < Nbias) ? bias[col] : 0.f;
            float b1 = (col + 1 < Nbias) ? bias[col + 1] : 0.f;
            #pragma unroll
            for (int h = 0; h < 2; h++) {
                int row = bm * 128 + rl0 + h * 8;
                float v0 = fmaxf(acc[mt][nt][2 * h + 0] + b0, 0.f);
                float v1 = fmaxf(acc[mt][nt][2 * h + 1] + b1, 0.f);
                *(float2*)(O + (size_t)row * Nstr + col) = make_float2(v0, v1);
                if (Sh) {
                    __half2 p; p.x = __float2half_rn(v0); p.y = __float2half_rn(v1);
                    *(__half2*)(Sh + (size_t)row * KSTR + col) = p;
                }
            }
        }
    }
}

// ---------------- mean pool ----------------------------------------------------
__global__ void pool_kernel(const float* __restrict__ h3, float* __restrict__ out) {
    int b = blockIdx.x;
    int chunk = blockIdx.y;
    int t = threadIdx.x;
    if (t >= 125) return;
    int o = chunk * 125 + t;
    const float* p = h3 + (size_t)(b * 512) * CLSP + o;
    float s = 0.f;
    for (int r = 0; r < 512; r++) s += p[(size_t)r * CLSP];
    out[b * CLS + o] = s * (1.0f / 512.0f);
}

// ---------------- launch --------------------------------------------------------
#define DIST_SMEM (128 * 136 * 2 * 2)   // 69632
#define SAGE_SMEM (6 * TB)              // 61440

extern "C" void kernel_launch(void* const* d_in, const int* in_sizes, int n_in,
                              void* d_out, int out_size) {
    const float* x   = (const float*)d_in[0];
    const float* wl0 = (const float*)d_in[1];
    const float* bl0 = (const float*)d_in[2];
    const float* wr0 = (const float*)d_in[3];
    const float* wl1 = (const float*)d_in[4];
    const float* bl1 = (const float*)d_in[5];
    const float* wr1 = (const float*)d_in[6];
    const float* wl2 = (const float*)d_in[7];
    const float* bl2 = (const float*)d_in[8];
    const float* wr2 = (const float*)d_in[9];
    float* out = (float*)d_out;

    f16 *c0h, *c1h, *w0h, *w0l, *w1h, *w1l, *w2h, *w2l;
    float *h1, *h2, *h3;
    cudaGetSymbolAddress((void**)&c0h, g_c0h);
    cudaGetSymbolAddress((void**)&c1h, g_c1h);
    cudaGetSymbolAddress((void**)&w0h, g_w0h);
    cudaGetSymbolAddress((void**)&w0l, g_w0l);
    cudaGetSymbolAddress((void**)&w1h, g_w1h);
    cudaGetSymbolAddress((void**)&w1l, g_w1l);
    cudaGetSymbolAddress((void**)&w2h, g_w2h);
    cudaGetSymbolAddress((void**)&w2l, g_w2l);
    cudaGetSymbolAddress((void**)&h1, g_h1);
    cudaGetSymbolAddress((void**)&h2, g_h2);
    cudaGetSymbolAddress((void**)&h3, g_h3);

    cudaFuncSetAttribute(dist_half, cudaFuncAttributeMaxDynamicSharedMemorySize, DIST_SMEM);
    cudaFuncSetAttribute(sage_mma, cudaFuncAttributeMaxDynamicSharedMemorySize, SAGE_SMEM);

    sq_kernel<<<NN / 8, 256>>>(x);                                   // 1
    xsplit_kernel<<<(NN * FEA + 255) / 256, 256>>>(x);               // 2
    wt_build01<<<dim3(512, 2), 256>>>(wl0, wr0, wl1, wr1);           // 3
    wt_build2<<<(1024 * 512 + 255) / 256, 256>>>(wl2, wr2);          // 4
    dist_half<<<dim3(64, 64), 256, DIST_SMEM>>>(c0h + 192);          // 5 (profiled)
    topk_refine<<<NN, 256>>>(x);                                     // 6

    // layer 0: [agg(x) | x], K=384
    gather_split<<<NN / 4, dim3(FEA / 4, 4)>>>(x, FEA, c0h);
    sage_mma<<<dim3(2, 64), 256, SAGE_SMEM>>>(c0h, 384, w0h, w0l, bl0, HID,
                                              h1, HID, c1h + 256);
    // layer 1: [agg(h1) | h1], K=512
    gather_split<<<NN / 4, dim3(HID / 4, 4)>>>(h1, HID, c1h);
    sage_mma<<<dim3(2, 64), 256, SAGE_SMEM>>>(c1h, 512, w1h, w1l, bl1, HID,
                                              h2, HID, c0h + 256);
    // layer 2: [agg(h2) | h2], K=512, N padded 1024
    gather_split<<<NN / 4, dim3(HID / 4, 4)>>>(h2, HID, c0h);
    sage_mma<<<dim3(8, 64), 256, SAGE_SMEM>>>(c0h, 512, w2h, w2l, bl2, CLS,
                                              h3, CLSP, (f16*)nullptr);

    pool_kernel<<<dim3(16, 8), 128>>>(h3, out);
}